// round 5
// baseline (speedup 1.0000x reference)
#include <cuda_runtime.h>
#include <cuda_bf16.h>

// Fully fused: every block redundantly computes the composite coefficients
// (cheap: ~9.5K FMA over 256 threads), then processes 2 positions per thread.
//
// Composite coefficients, per head h (4 heads), base = h*25:
//   [0..8]   P[i][j]  : u_i = sum_j P[i][j]*z_last[j] + p[i]    (scaled by 1/sqrt(dk))
//   [9..11]  p[i]
//   [12..14] r[i]     : d = sum_i r[i]*z_last[i] + s
//   [15]     s
//   [16..24] G[c][i]  : out[c] += sum_i G[c][i]*zbar[i]
// [100..102] g0[c]    : constant output term

__global__ void __launch_bounds__(256) attn_fused_kernel(
    const float* __restrict__ z,
    const float* __restrict__ W_in, const float* __restrict__ b_in,
    const float* __restrict__ W_q,  const float* __restrict__ b_q,
    const float* __restrict__ W_k,  const float* __restrict__ b_k,
    const float* __restrict__ W_v,  const float* __restrict__ b_v,
    const float* __restrict__ W_o,  const float* __restrict__ b_o,
    float* __restrict__ out, int n_pairs)
{
    __shared__ float Aq[32][3], Ak[32][3], Av[32][3];
    __shared__ float cq[32], ck[32], cv[32];
    __shared__ float C[104];

    const int t = threadIdx.x;

    // ---- Phase 1: compose q/k/v with the input projection ----
    for (int idx = t; idx < 96; idx += 256) {
        const int o = idx / 3, i = idx % 3;
        float aq = 0.f, ak = 0.f, av = 0.f;
#pragma unroll
        for (int j = 0; j < 32; j++) {
            const float win = W_in[j * 3 + i];
            aq += W_q[o * 32 + j] * win;
            ak += W_k[o * 32 + j] * win;
            av += W_v[o * 32 + j] * win;
        }
        Aq[o][i] = aq; Ak[o][i] = ak; Av[o][i] = av;
    }
    if (t < 32) {
        const int o = t;
        float q = b_q[o], k = b_k[o], v = b_v[o];
#pragma unroll
        for (int j = 0; j < 32; j++) {
            const float bi = b_in[j];
            q += W_q[o * 32 + j] * bi;
            k += W_k[o * 32 + j] * bi;
            v += W_v[o * 32 + j] * bi;
        }
        cq[o] = q; ck[o] = k; cv[o] = v;
    }
    __syncthreads();

    // ---- Phase 2: per-head bilinear composites into C[] ----
    const float scale = 0.35355339059327373f;   // 1/sqrt(8)
    for (int idx = t; idx < 103; idx += 256) {
        if (idx < 100) {
            const int h = idx / 25, e = idx % 25;
            const int base = h * 8;
            float val = 0.f;
            if (e < 9) {
                const int i = e / 3, j = e % 3;
#pragma unroll
                for (int d = 0; d < 8; d++) val += Ak[base + d][i] * Aq[base + d][j];
                val *= scale;
            } else if (e < 12) {
                const int i = e - 9;
#pragma unroll
                for (int d = 0; d < 8; d++) val += Ak[base + d][i] * cq[base + d];
                val *= scale;
            } else if (e < 15) {
                const int i = e - 12;
#pragma unroll
                for (int d = 0; d < 8; d++) val += Aq[base + d][i] * ck[base + d];
                val *= scale;
            } else if (e == 15) {
#pragma unroll
                for (int d = 0; d < 8; d++) val += cq[base + d] * ck[base + d];
                val *= scale;
            } else {
                const int e2 = e - 16;
                const int c = e2 / 3, i = e2 % 3;
#pragma unroll
                for (int d = 0; d < 8; d++) val += W_o[c * 32 + base + d] * Av[base + d][i];
            }
            C[h * 25 + e] = val;
        } else {
            const int c = idx - 100;
            float val = b_o[c];
#pragma unroll
            for (int d = 0; d < 32; d++) val += W_o[c * 32 + d] * cv[d];
            C[100 + c] = val;
        }
    }
    __syncthreads();

    // ---- Phase 3: 2 adjacent positions per thread (float2) ----
    const int p = blockIdx.x * blockDim.x + threadIdx.x;
    if (p >= n_pairs) return;

    const int pos = p << 1;            // even position
    const int b   = pos >> 16;         // pos / 65536
    const int hw  = pos & 65535;       // pos % 65536 (even)

    // z layout (B, T=8, C=3, 65536): elem (b,t,c,hw) at ((b*8+t)*3+c)*65536 + hw
    const float2* zp = (const float2*)(z + (size_t)b * 1572864 + hw);
    float2 zz[8][3];
#pragma unroll
    for (int s = 0; s < 8; s++)
#pragma unroll
        for (int c = 0; c < 3; c++)
            zz[s][c] = zp[(s * 3 + c) * 32768];

#define ZC(s, c) (q ? zz[s][c].y : zz[s][c].x)

    float2 res[3];
#pragma unroll
    for (int q = 0; q < 2; q++) {
        const float zl0 = ZC(7, 0), zl1 = ZC(7, 1), zl2 = ZC(7, 2);
        float o0 = C[100], o1 = C[101], o2 = C[102];

#pragma unroll
        for (int h = 0; h < 4; h++) {
            const float* Ph = &C[h * 25];
            const float u0 = Ph[0] * zl0 + Ph[1] * zl1 + Ph[2] * zl2 + Ph[9];
            const float u1 = Ph[3] * zl0 + Ph[4] * zl1 + Ph[5] * zl2 + Ph[10];
            const float u2 = Ph[6] * zl0 + Ph[7] * zl1 + Ph[8] * zl2 + Ph[11];
            const float d  = Ph[12] * zl0 + Ph[13] * zl1 + Ph[14] * zl2 + Ph[15];

            float sc[8];
            float m = -1e30f;
#pragma unroll
            for (int s = 0; s < 8; s++) {
                sc[s] = u0 * ZC(s, 0) + u1 * ZC(s, 1) + u2 * ZC(s, 2) + d;
                m = fmaxf(m, sc[s]);
            }
            float sum = 0.f, zb0 = 0.f, zb1 = 0.f, zb2 = 0.f;
#pragma unroll
            for (int s = 0; s < 8; s++) {
                const float e = __expf(sc[s] - m);
                sum += e;
                zb0 += e * ZC(s, 0);
                zb1 += e * ZC(s, 1);
                zb2 += e * ZC(s, 2);
            }
            const float inv = __fdividef(1.f, sum);
            zb0 *= inv; zb1 *= inv; zb2 *= inv;
            o0 += Ph[16] * zb0 + Ph[17] * zb1 + Ph[18] * zb2;
            o1 += Ph[19] * zb0 + Ph[20] * zb1 + Ph[21] * zb2;
            o2 += Ph[22] * zb0 + Ph[23] * zb1 + Ph[24] * zb2;
        }
        if (q == 0) { res[0].x = o0; res[1].x = o1; res[2].x = o2; }
        else        { res[0].y = o0; res[1].y = o1; res[2].y = o2; }
    }
#undef ZC

    // out layout (B, 3, 65536): elem (b,c,hw) at (b*3+c)*65536 + hw
    float2* op = (float2*)(out + (size_t)b * 196608 + hw);
    op[0]     = res[0];
    op[32768] = res[1];
    op[65536] = res[2];
}

extern "C" void kernel_launch(void* const* d_in, const int* in_sizes, int n_in,
                              void* d_out, int out_size)
{
    const float* z    = (const float*)d_in[0];
    const float* W_in = (const float*)d_in[1];
    const float* b_in = (const float*)d_in[2];
    const float* W_q  = (const float*)d_in[3];
    const float* b_q  = (const float*)d_in[4];
    const float* W_k  = (const float*)d_in[5];
    const float* b_k  = (const float*)d_in[6];
    const float* W_v  = (const float*)d_in[7];
    const float* b_v  = (const float*)d_in[8];
    const float* W_o  = (const float*)d_in[9];
    const float* b_o  = (const float*)d_in[10];
    float* out = (float*)d_out;

    const int n_pos   = out_size / 3;       // 262144
    const int n_pairs = n_pos / 2;          // 131072
    const int threads = 256;
    const int blocks  = (n_pairs + threads - 1) / threads;   // 512

    attn_fused_kernel<<<blocks, threads>>>(z, W_in, b_in, W_q, b_q, W_k, b_k,
                                           W_v, b_v, W_o, b_o, out, n_pairs);
}